// round 15
// baseline (speedup 1.0000x reference)
#include <cuda_runtime.h>
#include <cuda_fp16.h>
#include <cstdint>

// Problem dims (fixed by the dataset)
#define B_ 64
#define T_ 2048
#define I_ 256
#define H_ 256
#define G4_ 1024  // 4*H

// Scratch for the input projection xz = x@Wx + b : [B,T,4H] fp32 (537 MB).
__device__ float g_xz[(size_t)B_ * T_ * G4_];

// Pack two floats into fp16x2 bits (full 32-bit, both halves)
__device__ __forceinline__ unsigned pack_h2(float a, float b) {
    __half2 h = __floats2half2_rn(a, b);
    return *reinterpret_cast<unsigned*>(&h);
}

// ---------------------------------------------------------------------------
// Kernel 1: xz = x@Wx + b via fp16 tensor cores (mma.sync.m16n8k16, f32 acc).
// (unchanged — known good)
// ---------------------------------------------------------------------------
__global__ __launch_bounds__(256) void gemm_xz_mma(
    const float* __restrict__ x, const float* __restrict__ Wx,
    const float* __restrict__ bias)
{
    __shared__ __half As[128][72];
    __shared__ __half Bs[128][72];

    const int tid  = threadIdx.x;
    const int warp = tid >> 5;
    const int lane = tid & 31;
    const int g    = lane >> 2;
    const int tg   = lane & 3;

    const int m0 = blockIdx.y * 128;
    const int n0 = blockIdx.x * 128;
    const int wm = (warp & 3) * 32;
    const int wn = (warp >> 2) * 64;

    float d[2][8][4];
#pragma unroll
    for (int mt = 0; mt < 2; mt++)
#pragma unroll
        for (int nt = 0; nt < 8; nt++)
#pragma unroll
            for (int q = 0; q < 4; q++) d[mt][nt][q] = 0.f;

    const int sr = tid >> 1;
    const int sk = (tid & 1) * 32;

    for (int k0 = 0; k0 < 256; k0 += 64) {
        {
            const float4* xp = reinterpret_cast<const float4*>(
                &x[(size_t)(m0 + sr) * 256 + k0 + sk]);
#pragma unroll
            for (int i = 0; i < 8; i++) {
                float4 v = xp[i];
                *reinterpret_cast<__half2*>(&As[sr][sk + 4 * i])     = __floats2half2_rn(v.x, v.y);
                *reinterpret_cast<__half2*>(&As[sr][sk + 4 * i + 2]) = __floats2half2_rn(v.z, v.w);
            }
        }
        {
#pragma unroll
            for (int i = 0; i < 16; i++) {
                float w0 = __ldg(&Wx[(size_t)(k0 + sk + 2 * i) * 1024 + n0 + sr]);
                float w1 = __ldg(&Wx[(size_t)(k0 + sk + 2 * i + 1) * 1024 + n0 + sr]);
                *reinterpret_cast<__half2*>(&Bs[sr][sk + 2 * i]) = __floats2half2_rn(w0, w1);
            }
        }
        __syncthreads();

#pragma unroll
        for (int ks16 = 0; ks16 < 4; ks16++) {
            const int kc = ks16 * 16 + 2 * tg;
            unsigned a[2][4], b[8][2];
#pragma unroll
            for (int mt = 0; mt < 2; mt++) {
                const int r = wm + mt * 16 + g;
                a[mt][0] = *reinterpret_cast<const unsigned*>(&As[r][kc]);
                a[mt][1] = *reinterpret_cast<const unsigned*>(&As[r + 8][kc]);
                a[mt][2] = *reinterpret_cast<const unsigned*>(&As[r][kc + 8]);
                a[mt][3] = *reinterpret_cast<const unsigned*>(&As[r + 8][kc + 8]);
            }
#pragma unroll
            for (int nt = 0; nt < 8; nt++) {
                const int c = wn + nt * 8 + g;
                b[nt][0] = *reinterpret_cast<const unsigned*>(&Bs[c][kc]);
                b[nt][1] = *reinterpret_cast<const unsigned*>(&Bs[c][kc + 8]);
            }
#pragma unroll
            for (int mt = 0; mt < 2; mt++)
#pragma unroll
                for (int nt = 0; nt < 8; nt++) {
                    asm volatile(
                        "mma.sync.aligned.m16n8k16.row.col.f32.f16.f16.f32 "
                        "{%0,%1,%2,%3}, {%4,%5,%6,%7}, {%8,%9}, {%0,%1,%2,%3};"
                        : "+f"(d[mt][nt][0]), "+f"(d[mt][nt][1]),
                          "+f"(d[mt][nt][2]), "+f"(d[mt][nt][3])
                        : "r"(a[mt][0]), "r"(a[mt][1]), "r"(a[mt][2]), "r"(a[mt][3]),
                          "r"(b[nt][0]), "r"(b[nt][1]));
                }
        }
        __syncthreads();
    }

#pragma unroll
    for (int mt = 0; mt < 2; mt++) {
        const int r0 = m0 + wm + mt * 16 + g;
#pragma unroll
        for (int nt = 0; nt < 8; nt++) {
            const int c = n0 + wn + nt * 8 + 2 * tg;
            const float b0 = __ldg(&bias[c]);
            const float b1 = __ldg(&bias[c + 1]);
            float2 o0 = {d[mt][nt][0] + b0, d[mt][nt][1] + b1};
            float2 o1 = {d[mt][nt][2] + b0, d[mt][nt][3] + b1};
            *reinterpret_cast<float2*>(&g_xz[(size_t)r0 * 1024 + c])       = o0;
            *reinterpret_cast<float2*>(&g_xz[(size_t)(r0 + 8) * 1024 + c]) = o1;
        }
    }
}

// ---------------------------------------------------------------------------
// Kernel 2: LSTM scan, warp-autonomous. 8 clusters x 4 CTAs; 8 batches/cluster.
// GATE-INTERLEAVED tiles: mma A-tile row r = 4*u_off + gate, so each warp's
// 2 tiles cover 8 units x 4 gates x 8 batches -> the z exchange is
// WARP-LOCAL (EVEN stride 36 -> aligned float2 slots, conflict-free banks).
// NO __syncthreads in the loop. Sync = dual parity mbarriers fed by
// st.async complete_tx. Lane = updater for 1 unit x 2 batches; h-words
// built by bfly shuffle; 4 st.async; out[] STG unfenced.
// ---------------------------------------------------------------------------
__device__ __forceinline__ float tanhapx(float x) {
    float y;
    asm("tanh.approx.f32 %0, %1;" : "=f"(y) : "f"(x));
    return y;
}
__device__ __forceinline__ float sigapx(float x) {
    return fmaf(tanhapx(0.5f * x), 0.5f, 0.5f);
}

#define TX_BYTES 4096u  // per CTA per step: 4 CTAs x 256 lanes x 4 B
#define ZST 36          // exchange stride: EVEN (float2-aligned), mod32=4 (bank-spread)

__global__ __launch_bounds__(256, 1) __cluster_dims__(4, 1, 1)
void lstm_scan_mma(const float* __restrict__ Wh,
                   const float* __restrict__ h0,
                   const float* __restrict__ c0,
                   float* __restrict__ out)
{
    __shared__ unsigned hh2[2][128][8];              // [parity][k2][batch] fp16x2
    __shared__ alignas(16) float zw[8][8 * ZST];     // per-warp z: u*ZST + gate*8 + b
    __shared__ alignas(8) unsigned long long mbars[2];

    const int tid  = threadIdx.x;
    const int warp = tid >> 5;
    const int lane = tid & 31;
    const int g    = lane >> 2;   // 0..7
    const int tg   = lane & 3;    // 0..3

    unsigned rank;
    asm("mov.u32 %0, %%cluster_ctarank;" : "=r"(rank));
    const int b0    = (blockIdx.x >> 2) * 8;
    const int ubase = (int)rank * 64;

    // Gate-interleaved columns: tile c2 row r -> unit ubase+8*warp+4*c2+(r>>2),
    // gate r&3. Thread holds rows g and g+8 (unit +2, same gate).
    int cg[2], cg8[2];
#pragma unroll
    for (int c2 = 0; c2 < 2; c2++) {
        cg[c2]  = (g & 3) * 256 + ubase + warp * 8 + c2 * 4 + (g >> 2);
        cg8[c2] = cg[c2] + 2;
    }

    // ---- mbarrier init + initial arming ----
    const unsigned mbase = (unsigned)__cvta_generic_to_shared(&mbars[0]);
    if (tid == 0) {
        asm volatile("mbarrier.init.shared.b64 [%0], 1;" :: "r"(mbase) : "memory");
        asm volatile("mbarrier.init.shared.b64 [%0], 1;" :: "r"(mbase + 8) : "memory");
        asm volatile("mbarrier.arrive.expect_tx.shared.b64 _, [%0], %1;"
                     :: "r"(mbase), "r"(TX_BYTES) : "memory");
        asm volatile("mbarrier.arrive.expect_tx.shared.b64 _, [%0], %1;"
                     :: "r"(mbase + 8), "r"(TX_BYTES) : "memory");
    }

    // ---- Wh as stationary A-fragments (fp16), gate-interleaved cols ----
    unsigned wa[2][16][4];
#pragma unroll
    for (int c2 = 0; c2 < 2; c2++) {
#pragma unroll
        for (int kt = 0; kt < 16; kt++) {
            const int k0 = kt * 16 + 2 * tg;
            wa[c2][kt][0] = pack_h2(Wh[(size_t)(k0    ) * 1024 + cg[c2]],
                                    Wh[(size_t)(k0 + 1) * 1024 + cg[c2]]);
            wa[c2][kt][1] = pack_h2(Wh[(size_t)(k0    ) * 1024 + cg8[c2]],
                                    Wh[(size_t)(k0 + 1) * 1024 + cg8[c2]]);
            wa[c2][kt][2] = pack_h2(Wh[(size_t)(k0 + 8) * 1024 + cg[c2]],
                                    Wh[(size_t)(k0 + 9) * 1024 + cg[c2]]);
            wa[c2][kt][3] = pack_h2(Wh[(size_t)(k0 + 8) * 1024 + cg8[c2]],
                                    Wh[(size_t)(k0 + 9) * 1024 + cg8[c2]]);
        }
    }

    // ---- Init h buffer (parity 0) ----
    for (int i = tid; i < 128 * 8; i += 256) {
        const int k2 = i >> 3, b = i & 7;
        hh2[0][k2][b] = pack_h2(h0[(size_t)(b0 + b) * 256 + 2 * k2],
                                h0[(size_t)(b0 + b) * 256 + 2 * k2 + 1]);
    }

    // ---- Updater role: lane -> unit ubase+8*warp+(lane&7), batches b_l, b_l+4 ----
    const int u_l = lane & 7;
    const int b_l = lane >> 3;          // 0..3
    const int gu  = ubase + warp * 8 + u_l;
    float creg0 = c0[(size_t)(b0 + b_l)     * 256 + gu];
    float creg1 = c0[(size_t)(b0 + b_l + 4) * 256 + gu];

    const unsigned hbase = (unsigned)__cvta_generic_to_shared(&hh2[0][0][0]);
    const int k2u = gu >> 1;

    // xz bases for the accumulator slots (batches 2tg, 2tg+1)
    const float* xzA = g_xz + (size_t)(b0 + 2 * tg) * T_ * 1024;
    const float* xzB = xzA + (size_t)T_ * 1024;

    // Preload xz for t=0
    float xzr[2][4];
#pragma unroll
    for (int c2 = 0; c2 < 2; c2++) {
        xzr[c2][0] = __ldg(xzA + cg[c2]);
        xzr[c2][1] = __ldg(xzB + cg[c2]);
        xzr[c2][2] = __ldg(xzA + cg8[c2]);
        xzr[c2][3] = __ldg(xzB + cg8[c2]);
    }

    __syncthreads();
    asm volatile("barrier.cluster.arrive.aligned;" ::: "memory");
    asm volatile("barrier.cluster.wait.aligned;" ::: "memory");

    int ph0 = 0, ph1 = 0;

    for (int t = 0; t < T_; t++) {
        const int p = t & 1;

        float d[2][4], e[2][4];
#pragma unroll
        for (int c2 = 0; c2 < 2; c2++)
#pragma unroll
            for (int q = 0; q < 4; q++) { d[c2][q] = xzr[c2][q]; e[c2][q] = 0.f; }

        // ---- Wait for this parity's h traffic ----
        if (t > 0) {
            const unsigned mb = mbase + (unsigned)(p * 8);
            const int par = p ? ph1 : ph0;
            unsigned done;
            asm volatile(
                "{\n\t.reg .pred P1;\n\t"
                "mbarrier.try_wait.parity.acquire.cluster.shared::cta.b64 P1, [%1], %2;\n\t"
                "selp.b32 %0, 1, 0, P1;\n\t}"
                : "=r"(done) : "r"(mb), "r"(par) : "memory");
            if (!done) {
                asm volatile(
                    "{\n\t.reg .pred P1;\n\t"
                    "WAIT_%=:\n\t"
                    "mbarrier.try_wait.parity.acquire.cluster.shared::cta.b64 P1, [%0], %1, 0x989680;\n\t"
                    "@P1 bra.uni DONE_%=;\n\t"
                    "bra.uni WAIT_%=;\n\t"
                    "DONE_%=:\n\t}"
                    :: "r"(mb), "r"(par) : "memory");
            }
            if (p) ph1 ^= 1; else ph0 ^= 1;
            if (tid == 0)
                asm volatile("mbarrier.arrive.expect_tx.shared.b64 _, [%0], %1;"
                             :: "r"(mb), "r"(TX_BYTES) : "memory");
        }

        // Prefetch xz for t+1
        {
            const size_t off = (size_t)((t + 1 < T_) ? (t + 1) : t) * 1024;
#pragma unroll
            for (int c2 = 0; c2 < 2; c2++) {
                xzr[c2][0] = __ldg(xzA + off + cg[c2]);
                xzr[c2][1] = __ldg(xzB + off + cg[c2]);
                xzr[c2][2] = __ldg(xzA + off + cg8[c2]);
                xzr[c2][3] = __ldg(xzB + off + cg8[c2]);
            }
        }

        // ---- z += h @ Wh : 16 k-tiles, split accumulator chains ----
        const unsigned hp = hbase + (unsigned)(p * 4096);
#pragma unroll
        for (int kt = 0; kt < 16; kt++) {
            unsigned bw0, bw1;
            asm volatile("ld.shared.u32 %0, [%1];"
                         : "=r"(bw0) : "r"(hp + (unsigned)(((kt * 8 + tg) * 8 + g) * 4)));
            asm volatile("ld.shared.u32 %0, [%1];"
                         : "=r"(bw1) : "r"(hp + (unsigned)(((kt * 8 + 4 + tg) * 8 + g) * 4)));
            float (*acc)[4] = (kt < 8) ? d : e;
#pragma unroll
            for (int c2 = 0; c2 < 2; c2++) {
                asm volatile(
                    "mma.sync.aligned.m16n8k16.row.col.f32.f16.f16.f32 "
                    "{%0,%1,%2,%3}, {%4,%5,%6,%7}, {%8,%9}, {%0,%1,%2,%3};"
                    : "+f"(acc[c2][0]), "+f"(acc[c2][1]), "+f"(acc[c2][2]), "+f"(acc[c2][3])
                    : "r"(wa[c2][kt][0]), "r"(wa[c2][kt][1]),
                      "r"(wa[c2][kt][2]), "r"(wa[c2][kt][3]),
                      "r"(bw0), "r"(bw1));
            }
        }

        // ---- WARP-LOCAL z exchange: zw[warp][u*ZST + gate*8 + b] ----
        float* zp = zw[warp];
#pragma unroll
        for (int c2 = 0; c2 < 2; c2++) {
            const int idx0 = (4 * c2 + (g >> 2)) * ZST + (g & 3) * 8 + 2 * tg;
            float2 lo = {d[c2][0] + e[c2][0], d[c2][1] + e[c2][1]};
            float2 hi = {d[c2][2] + e[c2][2], d[c2][3] + e[c2][3]};
            *reinterpret_cast<float2*>(&zp[idx0])           = lo;   // unit
            *reinterpret_cast<float2*>(&zp[idx0 + 2 * ZST]) = hi;   // unit+2
        }
        __syncwarp();

        // ---- Gates + cell update (1 unit x 2 batches per lane) ----
        float hb, hb4;
        {
            const int zi0 = u_l * ZST + b_l;
            float zi = zp[zi0],      zf = zp[zi0 + 8];
            float zg = zp[zi0 + 16], zo = zp[zi0 + 24];
            float gi = sigapx(zi), gf = sigapx(zf);
            float gg = tanhapx(zg), go = sigapx(zo);
            creg0 = gf * creg0 + gi * gg;
            hb = go * tanhapx(creg0);

            zi = zp[zi0 + 4];      zf = zp[zi0 + 12];
            zg = zp[zi0 + 20];     zo = zp[zi0 + 28];
            gi = sigapx(zi); gf = sigapx(zf);
            gg = tanhapx(zg); go = sigapx(zo);
            creg1 = gf * creg1 + gi * gg;
            hb4 = go * tanhapx(creg1);
        }

        // ---- Build k-pair word with partner lane (unit^1), scatter ----
        {
            float ob  = __shfl_xor_sync(0xffffffffu, hb, 1);
            float ob4 = __shfl_xor_sync(0xffffffffu, hb4, 1);
            unsigned hw;
            int tb;
            if (gu & 1) { hw = pack_h2(ob4, hb4); tb = b_l + 4; }
            else        { hw = pack_h2(hb, ob);   tb = b_l; }

            const int np = p ^ 1;
            const unsigned doff = hbase + (unsigned)(np * 4096 + (k2u * 8 + tb) * 4);
            const unsigned moff = mbase + (unsigned)(np * 8);
#pragma unroll
            for (unsigned rr = 0; rr < 4; rr++) {
                unsigned ra, rb;
                asm("mapa.shared::cluster.u32 %0, %1, %2;" : "=r"(ra) : "r"(doff), "r"(rr));
                asm("mapa.shared::cluster.u32 %0, %1, %2;" : "=r"(rb) : "r"(moff), "r"(rr));
                asm volatile(
                    "st.async.weak.shared::cluster.mbarrier::complete_tx::bytes.b32 [%0], %1, [%2];"
                    :: "r"(ra), "r"(hw), "r"(rb) : "memory");
            }
        }

        // ---- Output stores (unfenced; drain overlaps next step) ----
        out[((size_t)(b0 + b_l)     * T_ + t) * 256 + gu] = hb;
        out[((size_t)(b0 + b_l + 4) * T_ + t) * 256 + gu] = hb4;
    }

    // Drain final parity-0 traffic, then exit rendezvous.
    asm volatile(
        "{\n\t.reg .pred P1;\n\t"
        "WAITF_%=:\n\t"
        "mbarrier.try_wait.parity.acquire.cluster.shared::cta.b64 P1, [%0], %1, 0x989680;\n\t"
        "@P1 bra.uni DONEF_%=;\n\t"
        "bra.uni WAITF_%=;\n\t"
        "DONEF_%=:\n\t}"
        :: "r"(mbase), "r"(ph0) : "memory");
    asm volatile("barrier.cluster.arrive.aligned;" ::: "memory");
    asm volatile("barrier.cluster.wait.aligned;" ::: "memory");
}

// ---------------------------------------------------------------------------
extern "C" void kernel_launch(void* const* d_in, const int* in_sizes, int n_in,
                              void* d_out, int out_size)
{
    const float* x    = (const float*)d_in[0];
    const float* Wx   = (const float*)d_in[1];
    const float* Wh   = (const float*)d_in[2];
    const float* bias = (const float*)d_in[3];
    const float* h0   = (const float*)d_in[4];
    const float* c0   = (const float*)d_in[5];
    float* out = (float*)d_out;

    // Phase 1: input projection (fp16 tensor cores)
    dim3 g1(1024 / 128, (B_ * T_) / 128);  // (8, 1024)
    gemm_xz_mma<<<g1, 256>>>(x, Wx, bias);

    // Phase 2: recurrent scan (8 clusters of 4 CTAs, 8 batches each)
    lstm_scan_mma<<<32, 256>>>(Wh, h0, c0, out);
}